// round 5
// baseline (speedup 1.0000x reference)
#include <cuda_runtime.h>
#include <cuda_bf16.h>
#include <cstdint>
#include <math.h>

// ---------------- problem constants ----------------
constexpr int N_NODES = 50000;
constexpr int N0      = 30000;
constexpr int N_EDGES = 600000;
constexpr int NT      = 8;
constexpr int K_TOT   = 1152;          // 8*128 rel + 128 root
constexpr int KC      = 64;
constexpr int NCHUNK  = K_TOT / KC;    // 18 (16 agg + 2 root)
constexpr int TILES0  = 235;           // ceil(30000/128)
constexpr int TILES1  = 157;           // ceil(20000/128)
constexpr int SEG     = NT * N_NODES;  // 400000 CSR segments, key = t*N + d
constexpr int NBLK    = (SEG + 1023) / 1024;  // 391

// ---------------- device scratch ----------------
__device__ float g_h1r[(size_t)N_NODES * 128];     // relu(h1), 25.6 MB
__device__ int   g_cnt[SEG];
__device__ int   g_off[SEG + 1];
__device__ int   g_cur[SEG];
__device__ float g_inv[SEG];
__device__ int   g_esrc[N_EDGES];
__device__ int   g_edst[N_EDGES];
__device__ int   g_bsum[NBLK];
__device__ int   g_bpre[NBLK];
__device__ __align__(16) __nv_bfloat16 g_B1h[2 * 128 * K_TOT];
__device__ __align__(16) __nv_bfloat16 g_B1l[2 * 128 * K_TOT];
__device__ __align__(16) __nv_bfloat16 g_B2h[2 * 40 * K_TOT];
__device__ __align__(16) __nv_bfloat16 g_B2l[2 * 40 * K_TOT];

// ---------------- helpers ----------------
__device__ __forceinline__ uint32_t smem_u32(const void* p) {
    uint32_t a;
    asm("{ .reg .u64 t; cvta.to.shared.u64 t, %1; cvt.u32.u64 %0, t; }" : "=r"(a) : "l"(p));
    return a;
}
__device__ __forceinline__ uint32_t pack_bf16x2(float a, float b) {
    __nv_bfloat162 t = __floats2bfloat162_rn(a, b);
    return *reinterpret_cast<uint32_t*>(&t);
}
__device__ __forceinline__ void ldsm_x4(uint32_t addr, uint32_t* r) {
    asm volatile("ldmatrix.sync.aligned.m8n8.x4.shared.b16 {%0,%1,%2,%3}, [%4];"
                 : "=r"(r[0]), "=r"(r[1]), "=r"(r[2]), "=r"(r[3]) : "r"(addr));
}
__device__ __forceinline__ void ldsm_x2(uint32_t addr, uint32_t* r) {
    asm volatile("ldmatrix.sync.aligned.m8n8.x2.shared.b16 {%0,%1}, [%2];"
                 : "=r"(r[0]), "=r"(r[1]) : "r"(addr));
}
__device__ __forceinline__ void mma_bf16(float* c, const uint32_t* a, uint32_t b0, uint32_t b1) {
    asm volatile(
        "mma.sync.aligned.m16n8k16.row.col.f32.bf16.bf16.f32 "
        "{%0,%1,%2,%3}, {%4,%5,%6,%7}, {%8,%9}, {%0,%1,%2,%3};"
        : "+f"(c[0]), "+f"(c[1]), "+f"(c[2]), "+f"(c[3])
        : "r"(a[0]), "r"(a[1]), "r"(a[2]), "r"(a[3]), "r"(b0), "r"(b1));
}

// ---------------- CSR build ----------------
__global__ void count_kernel(const int* __restrict__ dst, const int* __restrict__ et) {
    int e = blockIdx.x * blockDim.x + threadIdx.x;
    if (e < N_EDGES) atomicAdd(&g_cnt[et[e] * N_NODES + dst[e]], 1);
}

__global__ void scanA_kernel() {
    __shared__ int sm[256];
    int base = blockIdx.x * 1024 + threadIdx.x * 4;
    int s = 0;
#pragma unroll
    for (int j = 0; j < 4; j++) { int i = base + j; if (i < SEG) s += g_cnt[i]; }
    sm[threadIdx.x] = s; __syncthreads();
    for (int off = 128; off > 0; off >>= 1) {
        if (threadIdx.x < off) sm[threadIdx.x] += sm[threadIdx.x + off];
        __syncthreads();
    }
    if (threadIdx.x == 0) g_bsum[blockIdx.x] = sm[0];
}

__global__ void scanB_kernel() {
    __shared__ int sm[512];
    int tid = threadIdx.x;
    int v = (tid < NBLK) ? g_bsum[tid] : 0;
    sm[tid] = v; __syncthreads();
    for (int off = 1; off < 512; off <<= 1) {
        int t = (tid >= off) ? sm[tid - off] : 0;
        __syncthreads();
        sm[tid] += t;
        __syncthreads();
    }
    if (tid < NBLK) g_bpre[tid] = sm[tid] - v;
    if (tid == 0) g_off[SEG] = N_EDGES;
}

__global__ void scanC_kernel() {
    __shared__ int sm[256];
    int tid = threadIdx.x;
    int base = blockIdx.x * 1024 + tid * 4;
    int c[4]; int ls = 0;
#pragma unroll
    for (int j = 0; j < 4; j++) { int i = base + j; c[j] = (i < SEG) ? g_cnt[i] : 0; ls += c[j]; }
    sm[tid] = ls; __syncthreads();
    for (int off = 1; off < 256; off <<= 1) {
        int t = (tid >= off) ? sm[tid - off] : 0;
        __syncthreads();
        sm[tid] += t;
        __syncthreads();
    }
    int run = g_bpre[blockIdx.x] + sm[tid] - ls;
#pragma unroll
    for (int j = 0; j < 4; j++) {
        int i = base + j;
        if (i < SEG) {
            g_off[i] = run; g_cur[i] = run;
            g_inv[i] = 1.0f / (float)(c[j] < 1 ? 1 : c[j]);
            run += c[j];
        }
    }
}

__global__ void scatter_kernel(const int* __restrict__ src, const int* __restrict__ dst,
                               const int* __restrict__ et) {
    int e = blockIdx.x * blockDim.x + threadIdx.x;
    if (e >= N_EDGES) return;
    int d = dst[e];
    int key = et[e] * N_NODES + d;
    int pos = atomicAdd(&g_cur[key], 1);
    g_esrc[pos] = src[e];
    g_edst[pos] = d;
}

// ---------------- B prep ----------------
template<int NB>
__global__ void prepB_kernel(const float* __restrict__ rel_w, const float* __restrict__ root_w,
                             __nv_bfloat16* __restrict__ Bh, __nv_bfloat16* __restrict__ Bl)
{
    int i = blockIdx.x * blockDim.x + threadIdx.x;
    if (i >= 2 * NB * K_TOT) return;
    int k = i % K_TOT;
    int n = (i / K_TOT) % NB;
    int v = i / (K_TOT * NB);
    float w = (k < NT * 128) ? rel_w[(k >> 7) * NB * 128 + n * 128 + (k & 127)]
                             : root_w[v * NB * 128 + n * 128 + (k - NT * 128)];
    __nv_bfloat16 h = __float2bfloat16(w);
    Bh[i] = h;
    Bl[i] = __float2bfloat16(w - __bfloat162float(h));
}

// ---------------- fused aggregate + bf16x3 mma.sync GEMM ----------------
// Per 128-row tile, per chunk (t,half): segment-gather edges from CSR into SMEM fp32
// accumulator, scale by 1/cnt, split to bf16 hi/lo, MMA with 3 passes.
// EPI 0: relu(D+bias) -> outp[row*128+n];  EPI 1: log_softmax(D+bias) -> outp[row*40+n]
constexpr int ACC_STRIDE = 68;                      // fp32 words per accum row (bank-friendly)
constexpr int ACC_BYTES  = 128 * ACC_STRIDE * 4;    // 34816
constexpr int A_BYTES    = 128 * KC * 2;            // 16384

template<int NB, int SRC, int EPI>
__global__ void __launch_bounds__(256, 2) gemm_fused(
    const float* __restrict__ R0, const float* __restrict__ R1,
    const __nv_bfloat16* __restrict__ Bh, const __nv_bfloat16* __restrict__ Bl,
    const float* __restrict__ bias, float* __restrict__ outp)
{
    constexpr int WARPS_M = (NB == 128) ? 4 : 8;
    constexpr int WM = 128 / WARPS_M;
    constexpr int WN = (NB == 128) ? 64 : 40;
    constexpr int MF = WM / 16;
    constexpr int NF = WN / 8;
    constexpr int B_BYTES = NB * KC * 2;

    extern __shared__ char smem[];
    float* accum = (float*)smem;                    // [128][ACC_STRIDE]
    char* sAh = smem + ACC_BYTES;
    char* sAl = smem + ACC_BYTES + A_BYTES;
    char* sBh = smem + ACC_BYTES + 2 * A_BYTES;
    char* sBl = smem + ACC_BYTES + 2 * A_BYTES + B_BYTES;
    const uint32_t uAh = smem_u32(sAh), uAl = uAh + A_BYTES;
    const uint32_t uBh = uAh + 2 * A_BYTES, uBl = uBh + B_BYTES;

    const int tid  = threadIdx.x;
    const int wid  = tid >> 5;
    const int lane = tid & 31;
    const int warpM = wid % WARPS_M;
    const int warpN = wid / WARPS_M;

    const int bx = blockIdx.x;
    const int var = (bx < TILES0) ? 0 : 1;
    const int mrow0 = var ? (N0 + (bx - TILES0) * 128) : (bx * 128);
    const int row_end = var ? N_NODES : N0;
    const int tile_rows = min(128, row_end - mrow0);
    const __nv_bfloat16* Bhv = Bh + (size_t)var * NB * K_TOT;
    const __nv_bfloat16* Blv = Bl + (size_t)var * NB * K_TOT;
    const float* biasv = bias + var * NB;

    // zero accumulator tile
    for (int i = tid; i < 128 * ACC_STRIDE / 4; i += 256)
        ((float4*)accum)[i] = make_float4(0.f, 0.f, 0.f, 0.f);

    float acc[MF][NF][4];
#pragma unroll
    for (int i = 0; i < MF; i++)
#pragma unroll
        for (int j = 0; j < NF; j++)
#pragma unroll
            for (int q = 0; q < 4; q++) acc[i][j][q] = 0.f;

    const int crow = tid & 127;               // convert mapping: conflict-free phases
    const int chalf = tid >> 7;                // 0/1 -> cols [0,32) / [32,64)
    __syncthreads();

    for (int c = 0; c < NCHUNK; c++) {
        const int h = c & 1;
        if (c < 16) {
            const int t = c >> 1;
            // ---- edge segment gather -> SMEM fp32 accumulate ----
            const int kb = t * N_NODES + mrow0;
            const int o0 = g_off[kb];
            const int o1 = g_off[kb + tile_rows];
            for (int e = o0 + wid; e < o1; e += 8) {
                int s = g_esrc[e], d = g_edst[e];
                const float* xs = (SRC == 0)
                    ? ((s < N0) ? R0 + (size_t)s * 128 : R1 + (size_t)(s - N0) * 128)
                    : R0 + (size_t)s * 128;
                float2 v = *reinterpret_cast<const float2*>(xs + h * 64 + lane * 2);
                float* ap = &accum[(d - mrow0) * ACC_STRIDE + lane * 2];
                atomicAdd(ap,     v.x);
                atomicAdd(ap + 1, v.y);
            }
            __syncthreads();
            // ---- scale + convert to bf16 hi/lo (swizzled), re-zero accum ----
            {
                float invv = 0.f;
                if (crow < tile_rows) invv = g_inv[t * N_NODES + mrow0 + crow];
                float* arow = &accum[crow * ACC_STRIDE + chalf * 32];
#pragma unroll
                for (int j = 0; j < 4; j++) {
                    float4 p = ((float4*)(arow + j * 8))[0];
                    float4 q = ((float4*)(arow + j * 8))[1];
                    p.x *= invv; p.y *= invv; p.z *= invv; p.w *= invv;
                    q.x *= invv; q.y *= invv; q.z *= invv; q.w *= invv;
                    uint4 hv, lv;
                    hv.x = pack_bf16x2(p.x, p.y); hv.y = pack_bf16x2(p.z, p.w);
                    hv.z = pack_bf16x2(q.x, q.y); hv.w = pack_bf16x2(q.z, q.w);
                    lv.x = pack_bf16x2(p.x - __bfloat162float(__float2bfloat16(p.x)),
                                       p.y - __bfloat162float(__float2bfloat16(p.y)));
                    lv.y = pack_bf16x2(p.z - __bfloat162float(__float2bfloat16(p.z)),
                                       p.w - __bfloat162float(__float2bfloat16(p.w)));
                    lv.z = pack_bf16x2(q.x - __bfloat162float(__float2bfloat16(q.x)),
                                       q.y - __bfloat162float(__float2bfloat16(q.y)));
                    lv.w = pack_bf16x2(q.z - __bfloat162float(__float2bfloat16(q.z)),
                                       q.w - __bfloat162float(__float2bfloat16(q.w)));
                    ((float4*)(arow + j * 8))[0] = make_float4(0.f, 0.f, 0.f, 0.f);
                    ((float4*)(arow + j * 8))[1] = make_float4(0.f, 0.f, 0.f, 0.f);
                    int u = chalf * 4 + j;
                    uint32_t off = crow * 128 + ((u ^ (crow & 7)) << 4);
                    *reinterpret_cast<uint4*>(sAh + off) = hv;
                    *reinterpret_cast<uint4*>(sAl + off) = lv;
                }
            }
        } else {
            // ---- root chunk: direct load of own-row features ----
#pragma unroll
            for (int i = 0; i < 4; i++) {
                int idx = tid + i * 256;            // 0..1023
                int row = idx >> 3;
                int u = idx & 7;
                float4 p = make_float4(0.f, 0.f, 0.f, 0.f), q = p;
                if (row < tile_rows) {
                    int d = mrow0 + row;
                    const float* xs = (SRC == 0)
                        ? ((d < N0) ? R0 + (size_t)d * 128 : R1 + (size_t)(d - N0) * 128)
                        : R0 + (size_t)d * 128;
                    p = *reinterpret_cast<const float4*>(xs + h * 64 + u * 8);
                    q = *reinterpret_cast<const float4*>(xs + h * 64 + u * 8 + 4);
                }
                uint4 hv, lv;
                hv.x = pack_bf16x2(p.x, p.y); hv.y = pack_bf16x2(p.z, p.w);
                hv.z = pack_bf16x2(q.x, q.y); hv.w = pack_bf16x2(q.z, q.w);
                lv.x = pack_bf16x2(p.x - __bfloat162float(__float2bfloat16(p.x)),
                                   p.y - __bfloat162float(__float2bfloat16(p.y)));
                lv.y = pack_bf16x2(p.z - __bfloat162float(__float2bfloat16(p.z)),
                                   p.w - __bfloat162float(__float2bfloat16(p.w)));
                lv.z = pack_bf16x2(q.x - __bfloat162float(__float2bfloat16(q.x)),
                                   q.y - __bfloat162float(__float2bfloat16(q.y)));
                lv.w = pack_bf16x2(q.z - __bfloat162float(__float2bfloat16(q.z)),
                                   q.w - __bfloat162float(__float2bfloat16(q.w)));
                uint32_t off = row * 128 + ((u ^ (row & 7)) << 4);
                *reinterpret_cast<uint4*>(sAh + off) = hv;
                *reinterpret_cast<uint4*>(sAl + off) = lv;
            }
        }
        // ---- B tile load (hi & lo), swizzled ----
        constexpr int BU = NB * 8;
        for (int idx = tid; idx < 2 * BU; idx += 256) {
            int isLo = idx >= BU;
            int ii = isLo ? idx - BU : idx;
            int n = ii >> 3;
            int u = ii & 7;
            uint4 val = *reinterpret_cast<const uint4*>(
                (isLo ? Blv : Bhv) + (size_t)n * K_TOT + c * KC + u * 8);
            uint32_t off = n * 128 + ((u ^ (n & 7)) << 4);
            *reinterpret_cast<uint4*>((isLo ? sBl : sBh) + off) = val;
        }
        __syncthreads();

        // ---- compute: 3 passes (AhBh, AhBl, AlBh) x 4 k16 steps ----
#pragma unroll
        for (int p = 0; p < 3; p++) {
            uint32_t aBase = (p == 2) ? uAl : uAh;
            uint32_t bBase = (p == 1) ? uBl : uBh;
#pragma unroll
            for (int ks = 0; ks < 4; ks++) {
                uint32_t a[MF][4];
#pragma unroll
                for (int mf = 0; mf < MF; mf++) {
                    int row = warpM * WM + mf * 16 + (lane & 15);
                    int u = 2 * ks + (lane >> 4);
                    ldsm_x4(aBase + row * 128 + ((u ^ (row & 7)) << 4), a[mf]);
                }
#pragma unroll
                for (int nfp = 0; nfp < NF / 2; nfp++) {
                    int nrow = warpN * WN + nfp * 16 + ((lane >> 4) * 8) + (lane & 7);
                    int u = 2 * ks + ((lane >> 3) & 1);
                    uint32_t b[4];
                    ldsm_x4(bBase + nrow * 128 + ((u ^ (nrow & 7)) << 4), b);
#pragma unroll
                    for (int mf = 0; mf < MF; mf++) {
                        mma_bf16(acc[mf][2 * nfp + 0], a[mf], b[0], b[1]);
                        mma_bf16(acc[mf][2 * nfp + 1], a[mf], b[2], b[3]);
                    }
                }
                if (NF & 1) {
                    int l = lane & 15;
                    int nrow = warpN * WN + (NF - 1) * 8 + (l & 7);
                    int u = 2 * ks + (l >> 3);
                    uint32_t b[2];
                    ldsm_x2(bBase + nrow * 128 + ((u ^ (nrow & 7)) << 4), b);
#pragma unroll
                    for (int mf = 0; mf < MF; mf++)
                        mma_bf16(acc[mf][NF - 1], a[mf], b[0], b[1]);
                }
            }
        }
        __syncthreads();
    }

    // ---- epilogue ----
    if (EPI == 0) {
#pragma unroll
        for (int mf = 0; mf < MF; mf++) {
#pragma unroll
            for (int nf = 0; nf < NF; nf++) {
                int col = warpN * WN + nf * 8 + (lane & 3) * 2;
                float b0 = biasv[col], b1 = biasv[col + 1];
                int r0 = mrow0 + warpM * WM + mf * 16 + (lane >> 2);
                if (r0 < row_end) {
                    float2 v = make_float2(fmaxf(acc[mf][nf][0] + b0, 0.f),
                                           fmaxf(acc[mf][nf][1] + b1, 0.f));
                    *reinterpret_cast<float2*>(outp + (size_t)r0 * 128 + col) = v;
                }
                int r1 = r0 + 8;
                if (r1 < row_end) {
                    float2 v = make_float2(fmaxf(acc[mf][nf][2] + b0, 0.f),
                                           fmaxf(acc[mf][nf][3] + b1, 0.f));
                    *reinterpret_cast<float2*>(outp + (size_t)r1 * 128 + col) = v;
                }
            }
        }
    } else {
#pragma unroll
        for (int h = 0; h < 2; h++) {
            int row = mrow0 + wid * 16 + (lane >> 2) + h * 8;
            float v[2 * NF];
            float m = -INFINITY;
#pragma unroll
            for (int f = 0; f < NF; f++) {
                int col = f * 8 + (lane & 3) * 2;
                v[2 * f + 0] = acc[0][f][2 * h + 0] + biasv[col];
                v[2 * f + 1] = acc[0][f][2 * h + 1] + biasv[col + 1];
                m = fmaxf(m, fmaxf(v[2 * f], v[2 * f + 1]));
            }
            m = fmaxf(m, __shfl_xor_sync(0xFFFFFFFFu, m, 1));
            m = fmaxf(m, __shfl_xor_sync(0xFFFFFFFFu, m, 2));
            float s = 0.f;
#pragma unroll
            for (int j = 0; j < 2 * NF; j++) s += expf(v[j] - m);
            s += __shfl_xor_sync(0xFFFFFFFFu, s, 1);
            s += __shfl_xor_sync(0xFFFFFFFFu, s, 2);
            float l = m + logf(s);
            if (row < row_end) {
#pragma unroll
                for (int f = 0; f < NF; f++) {
                    int col = f * 8 + (lane & 3) * 2;
                    float2 o = make_float2(v[2 * f] - l, v[2 * f + 1] - l);
                    *reinterpret_cast<float2*>(outp + (size_t)row * NB + col) = o;
                }
            }
        }
    }
}

// ---------------- launch ----------------
extern "C" void kernel_launch(void* const* d_in, const int* in_sizes, int n_in,
                              void* d_out, int out_size)
{
    const float* x0      = (const float*)d_in[0];
    const float* emb1    = (const float*)d_in[1];
    const float* rel_w1  = (const float*)d_in[2];
    const float* root_w1 = (const float*)d_in[3];
    const float* root_b1 = (const float*)d_in[4];
    const float* rel_w2  = (const float*)d_in[5];
    const float* root_w2 = (const float*)d_in[6];
    const float* root_b2 = (const float*)d_in[7];
    const int*   eidx    = (const int*)d_in[8];
    const int*   etype   = (const int*)d_in[9];
    (void)in_sizes; (void)n_in; (void)out_size;

    const int* src = eidx;
    const int* dst = eidx + N_EDGES;
    float* out = (float*)d_out;

    void *p_cnt, *p_h1r, *p_B1h, *p_B1l, *p_B2h, *p_B2l;
    cudaGetSymbolAddress(&p_cnt, g_cnt);
    cudaGetSymbolAddress(&p_h1r, g_h1r);
    cudaGetSymbolAddress(&p_B1h, g_B1h);
    cudaGetSymbolAddress(&p_B1l, g_B1l);
    cudaGetSymbolAddress(&p_B2h, g_B2h);
    cudaGetSymbolAddress(&p_B2l, g_B2l);

    constexpr int SMEM1 = ACC_BYTES + 2 * A_BYTES + 2 * 128 * KC * 2;  // 100352
    constexpr int SMEM2 = ACC_BYTES + 2 * A_BYTES + 2 * 40 * KC * 2;   // 77824
    cudaFuncSetAttribute(gemm_fused<128, 0, 0>, cudaFuncAttributeMaxDynamicSharedMemorySize, SMEM1);
    cudaFuncSetAttribute(gemm_fused<40, 1, 1>,  cudaFuncAttributeMaxDynamicSharedMemorySize, SMEM2);

    // B weight split (tiny)
    prepB_kernel<128><<<(2 * 128 * K_TOT + 255) / 256, 256>>>(
        rel_w1, root_w1, (__nv_bfloat16*)p_B1h, (__nv_bfloat16*)p_B1l);
    prepB_kernel<40><<<(2 * 40 * K_TOT + 255) / 256, 256>>>(
        rel_w2, root_w2, (__nv_bfloat16*)p_B2h, (__nv_bfloat16*)p_B2l);

    // CSR build: count -> scan -> scatter (+ 1/cnt table)
    cudaMemsetAsync(p_cnt, 0, sizeof(int) * SEG);
    count_kernel<<<(N_EDGES + 255) / 256, 256>>>(dst, etype);
    scanA_kernel<<<NBLK, 256>>>();
    scanB_kernel<<<1, 512>>>();
    scanC_kernel<<<NBLK, 256>>>();
    scatter_kernel<<<(N_EDGES + 255) / 256, 256>>>(src, dst, etype);

    // layer 1: fused aggregate + GEMM (rel + root + bias + relu) -> g_h1r
    gemm_fused<128, 0, 0><<<TILES0 + TILES1, 256, SMEM1>>>(
        x0, emb1, (const __nv_bfloat16*)p_B1h, (const __nv_bfloat16*)p_B1l,
        root_b1, (float*)p_h1r);

    // layer 2: fused aggregate + GEMM (rel + root + bias + log_softmax) -> d_out
    gemm_fused<40, 1, 1><<<TILES0 + TILES1, 256, SMEM2>>>(
        (const float*)p_h1r, nullptr, (const __nv_bfloat16*)p_B2h, (const __nv_bfloat16*)p_B2l,
        root_b2, out);
}

// round 6
// speedup vs baseline: 1.6195x; 1.6195x over previous
#include <cuda_runtime.h>
#include <cuda_bf16.h>
#include <cstdint>
#include <math.h>

// ---------------- problem constants ----------------
constexpr int N_NODES = 50000;
constexpr int N0      = 30000;
constexpr int N_EDGES = 600000;
constexpr int NT      = 8;
constexpr int K_TOT   = 1152;          // 8*128 rel + 128 root
constexpr int KC      = 64;
constexpr int NCHUNK  = K_TOT / KC;    // 18 (16 agg + 2 root)
constexpr int TILES0  = 235;           // ceil(30000/128)
constexpr int TILES1  = 157;           // ceil(20000/128)
constexpr int N_PAD   = (TILES0 + TILES1) * 128;   // 50176 padded rows
constexpr int SEG     = NT * N_NODES;  // 400000 CSR segments, key = t*N + d
constexpr int NBLK    = (SEG + 1023) / 1024;  // 391

// ---------------- device scratch ----------------
__device__ float g_h1r[(size_t)N_NODES * 128];     // relu(h1), 25.6 MB
__device__ int   g_cnt[SEG];
__device__ int   g_off[SEG + 1];
__device__ int   g_cur[SEG];
__device__ int   g_esrc[N_EDGES];
__device__ int   g_bsum[NBLK];
__device__ int   g_bpre[NBLK];
__device__ __align__(16) __nv_bfloat16 g_aggh[(size_t)N_PAD * 1024];  // 102.8 MB
__device__ __align__(16) __nv_bfloat16 g_aggl[(size_t)N_PAD * 1024];  // 102.8 MB
__device__ __align__(16) __nv_bfloat16 g_B1h[2 * 128 * K_TOT];
__device__ __align__(16) __nv_bfloat16 g_B1l[2 * 128 * K_TOT];
__device__ __align__(16) __nv_bfloat16 g_B2h[2 * 40 * K_TOT];
__device__ __align__(16) __nv_bfloat16 g_B2l[2 * 40 * K_TOT];

// ---------------- helpers ----------------
__device__ __forceinline__ uint32_t smem_u32(const void* p) {
    uint32_t a;
    asm("{ .reg .u64 t; cvta.to.shared.u64 t, %1; cvt.u32.u64 %0, t; }" : "=r"(a) : "l"(p));
    return a;
}
__device__ __forceinline__ uint32_t pack_bf16x2(float a, float b) {
    __nv_bfloat162 t = __floats2bfloat162_rn(a, b);
    return *reinterpret_cast<uint32_t*>(&t);
}
__device__ __forceinline__ void ldsm_x4(uint32_t addr, uint32_t* r) {
    asm volatile("ldmatrix.sync.aligned.m8n8.x4.shared.b16 {%0,%1,%2,%3}, [%4];"
                 : "=r"(r[0]), "=r"(r[1]), "=r"(r[2]), "=r"(r[3]) : "r"(addr));
}
__device__ __forceinline__ void ldsm_x2(uint32_t addr, uint32_t* r) {
    asm volatile("ldmatrix.sync.aligned.m8n8.x2.shared.b16 {%0,%1}, [%2];"
                 : "=r"(r[0]), "=r"(r[1]) : "r"(addr));
}
__device__ __forceinline__ void mma_bf16(float* c, const uint32_t* a, uint32_t b0, uint32_t b1) {
    asm volatile(
        "mma.sync.aligned.m16n8k16.row.col.f32.bf16.bf16.f32 "
        "{%0,%1,%2,%3}, {%4,%5,%6,%7}, {%8,%9}, {%0,%1,%2,%3};"
        : "+f"(c[0]), "+f"(c[1]), "+f"(c[2]), "+f"(c[3])
        : "r"(a[0]), "r"(a[1]), "r"(a[2]), "r"(a[3]), "r"(b0), "r"(b1));
}

// ---------------- CSR build ----------------
__global__ void count_kernel(const int* __restrict__ dst, const int* __restrict__ et) {
    int e = blockIdx.x * blockDim.x + threadIdx.x;
    if (e < N_EDGES) atomicAdd(&g_cnt[et[e] * N_NODES + dst[e]], 1);
}

__global__ void scanA_kernel() {
    __shared__ int sm[256];
    int base = blockIdx.x * 1024 + threadIdx.x * 4;
    int s = 0;
#pragma unroll
    for (int j = 0; j < 4; j++) { int i = base + j; if (i < SEG) s += g_cnt[i]; }
    sm[threadIdx.x] = s; __syncthreads();
    for (int off = 128; off > 0; off >>= 1) {
        if (threadIdx.x < off) sm[threadIdx.x] += sm[threadIdx.x + off];
        __syncthreads();
    }
    if (threadIdx.x == 0) g_bsum[blockIdx.x] = sm[0];
}

__global__ void scanB_kernel() {
    __shared__ int sm[512];
    int tid = threadIdx.x;
    int v = (tid < NBLK) ? g_bsum[tid] : 0;
    sm[tid] = v; __syncthreads();
    for (int off = 1; off < 512; off <<= 1) {
        int t = (tid >= off) ? sm[tid - off] : 0;
        __syncthreads();
        sm[tid] += t;
        __syncthreads();
    }
    if (tid < NBLK) g_bpre[tid] = sm[tid] - v;
    if (tid == 0) g_off[SEG] = N_EDGES;
}

__global__ void scanC_kernel() {
    __shared__ int sm[256];
    int tid = threadIdx.x;
    int base = blockIdx.x * 1024 + tid * 4;
    int c[4]; int ls = 0;
#pragma unroll
    for (int j = 0; j < 4; j++) { int i = base + j; c[j] = (i < SEG) ? g_cnt[i] : 0; ls += c[j]; }
    sm[tid] = ls; __syncthreads();
    for (int off = 1; off < 256; off <<= 1) {
        int t = (tid >= off) ? sm[tid - off] : 0;
        __syncthreads();
        sm[tid] += t;
        __syncthreads();
    }
    int run = g_bpre[blockIdx.x] + sm[tid] - ls;
#pragma unroll
    for (int j = 0; j < 4; j++) {
        int i = base + j;
        if (i < SEG) {
            g_off[i] = run; g_cur[i] = run;
            run += c[j];
        }
    }
}

__global__ void scatter_kernel(const int* __restrict__ src, const int* __restrict__ dst,
                               const int* __restrict__ et) {
    int e = blockIdx.x * blockDim.x + threadIdx.x;
    if (e >= N_EDGES) return;
    int key = et[e] * N_NODES + dst[e];
    int pos = atomicAdd(&g_cur[key], 1);
    g_esrc[pos] = src[e];
}

// ---------------- atomic-free aggregation: warp per (t,dst) segment ----------------
// agg[d][t*128+c] = (1/len) * sum_{e in seg} x[src(e)][c], written ONCE (zeros for empty).
template<int SRC>
__global__ void agg_kernel(const float* __restrict__ R0, const float* __restrict__ R1)
{
    int seg = (blockIdx.x * blockDim.x + threadIdx.x) >> 5;
    if (seg >= SEG) return;
    int lane = threadIdx.x & 31;
    int t = seg / N_NODES;
    int d = seg - t * N_NODES;
    int o0 = g_off[seg], o1 = g_off[seg + 1];
    float4 acc = make_float4(0.f, 0.f, 0.f, 0.f);
    for (int e = o0; e < o1; e++) {
        int s = g_esrc[e];
        const float* xs = (SRC == 0)
            ? ((s < N0) ? R0 + (size_t)s * 128 : R1 + (size_t)(s - N0) * 128)
            : R0 + (size_t)s * 128;
        float4 v = reinterpret_cast<const float4*>(xs)[lane];
        acc.x += v.x; acc.y += v.y; acc.z += v.z; acc.w += v.w;
    }
    int len = o1 - o0;
    float inv = 1.0f / (float)(len < 1 ? 1 : len);
    acc.x *= inv; acc.y *= inv; acc.z *= inv; acc.w *= inv;
    uint2 hv, lv;
    hv.x = pack_bf16x2(acc.x, acc.y);
    hv.y = pack_bf16x2(acc.z, acc.w);
    lv.x = pack_bf16x2(acc.x - __bfloat162float(__float2bfloat16(acc.x)),
                       acc.y - __bfloat162float(__float2bfloat16(acc.y)));
    lv.y = pack_bf16x2(acc.z - __bfloat162float(__float2bfloat16(acc.z)),
                       acc.w - __bfloat162float(__float2bfloat16(acc.w)));
    size_t o = (size_t)d * 1024 + t * 128 + lane * 4;
    *reinterpret_cast<uint2*>(g_aggh + o) = hv;
    *reinterpret_cast<uint2*>(g_aggl + o) = lv;
}

// ---------------- B prep ----------------
template<int NB>
__global__ void prepB_kernel(const float* __restrict__ rel_w, const float* __restrict__ root_w,
                             __nv_bfloat16* __restrict__ Bh, __nv_bfloat16* __restrict__ Bl)
{
    int i = blockIdx.x * blockDim.x + threadIdx.x;
    if (i >= 2 * NB * K_TOT) return;
    int k = i % K_TOT;
    int n = (i / K_TOT) % NB;
    int v = i / (K_TOT * NB);
    float w = (k < NT * 128) ? rel_w[(k >> 7) * NB * 128 + n * 128 + (k & 127)]
                             : root_w[v * NB * 128 + n * 128 + (k - NT * 128)];
    __nv_bfloat16 h = __float2bfloat16(w);
    Bh[i] = h;
    Bl[i] = __float2bfloat16(w - __bfloat162float(h));
}

// ---------------- bf16x3 mma.sync GEMM (A agg-chunks pre-split in gmem) ----------------
// EPI 0: relu(D+bias) -> outp[row*128+n];  EPI 1: log_softmax(D+bias) -> outp[row*40+n]
template<int NB, int SRC, int EPI>
__global__ void __launch_bounds__(256, 2) gemm_kernel(
    const float* __restrict__ R0, const float* __restrict__ R1,
    const __nv_bfloat16* __restrict__ Bh, const __nv_bfloat16* __restrict__ Bl,
    const float* __restrict__ bias, float* __restrict__ outp)
{
    constexpr int WARPS_M = (NB == 128) ? 4 : 8;
    constexpr int WARPS_N = (NB == 128) ? 2 : 1;
    constexpr int WM = 128 / WARPS_M;
    constexpr int WN = NB / WARPS_N;
    constexpr int MF = WM / 16;
    constexpr int NF = WN / 8;
    constexpr int A_BYTES = 128 * KC * 2;      // 16384
    constexpr int B_BYTES = NB * KC * 2;

    extern __shared__ char smem[];
    char* sAh = smem;
    char* sAl = smem + A_BYTES;
    char* sBh = smem + 2 * A_BYTES;
    char* sBl = smem + 2 * A_BYTES + B_BYTES;
    const uint32_t uAh = smem_u32(sAh), uAl = uAh + A_BYTES;
    const uint32_t uBh = uAh + 2 * A_BYTES, uBl = uBh + B_BYTES;

    const int tid  = threadIdx.x;
    const int wid  = tid >> 5;
    const int lane = tid & 31;
    const int warpM = wid % WARPS_M;
    const int warpN = wid / WARPS_M;

    const int bx = blockIdx.x;
    const int var = (bx < TILES0) ? 0 : 1;
    const int mrow0 = var ? (N0 + (bx - TILES0) * 128) : (bx * 128);
    const int row_end = var ? N_NODES : N0;
    const __nv_bfloat16* Bhv = Bh + (size_t)var * NB * K_TOT;
    const __nv_bfloat16* Blv = Bl + (size_t)var * NB * K_TOT;
    const float* biasv = bias + var * NB;

    float acc[MF][NF][4];
#pragma unroll
    for (int i = 0; i < MF; i++)
#pragma unroll
        for (int j = 0; j < NF; j++)
#pragma unroll
            for (int q = 0; q < 4; q++) acc[i][j][q] = 0.f;

    // padded agg rows for this tile (aligned, always in-bounds thanks to N_PAD)
    const size_t aggRow0 = (size_t)(var ? (N0 + (bx - TILES0) * 128) : bx * 128) * 1024;

    for (int c = 0; c < NCHUNK; c++) {
        if (c < 16) {
            // ---- A agg chunk: direct bf16 copy (hi & lo), swizzled ----
#pragma unroll
            for (int i = 0; i < 8; i++) {
                int idx = tid + i * 256;            // 0..2047
                int isLo = idx >= 1024;
                int ii = isLo ? idx - 1024 : idx;
                int row = ii >> 3;
                int u = ii & 7;
                const __nv_bfloat16* gp = (isLo ? g_aggl : g_aggh)
                    + aggRow0 + (size_t)row * 1024 + c * KC + u * 8;
                uint4 val = *reinterpret_cast<const uint4*>(gp);
                uint32_t off = row * 128 + ((u ^ (row & 7)) << 4);
                *reinterpret_cast<uint4*>((isLo ? sAl : sAh) + off) = val;
            }
        } else {
            // ---- root chunk: load own-row fp32, split to hi/lo ----
            const int h = c - 16;
#pragma unroll
            for (int i = 0; i < 4; i++) {
                int idx = tid + i * 256;            // 0..1023
                int row = idx >> 3;
                int u = idx & 7;
                float4 p = make_float4(0.f, 0.f, 0.f, 0.f), q = p;
                int d = mrow0 + row;
                if (d < row_end) {
                    const float* xs = (SRC == 0)
                        ? ((d < N0) ? R0 + (size_t)d * 128 : R1 + (size_t)(d - N0) * 128)
                        : R0 + (size_t)d * 128;
                    p = *reinterpret_cast<const float4*>(xs + h * 64 + u * 8);
                    q = *reinterpret_cast<const float4*>(xs + h * 64 + u * 8 + 4);
                }
                uint4 hv, lv;
                hv.x = pack_bf16x2(p.x, p.y); hv.y = pack_bf16x2(p.z, p.w);
                hv.z = pack_bf16x2(q.x, q.y); hv.w = pack_bf16x2(q.z, q.w);
                lv.x = pack_bf16x2(p.x - __bfloat162float(__float2bfloat16(p.x)),
                                   p.y - __bfloat162float(__float2bfloat16(p.y)));
                lv.y = pack_bf16x2(p.z - __bfloat162float(__float2bfloat16(p.z)),
                                   p.w - __bfloat162float(__float2bfloat16(p.w)));
                lv.z = pack_bf16x2(q.x - __bfloat162float(__float2bfloat16(q.x)),
                                   q.y - __bfloat162float(__float2bfloat16(q.y)));
                lv.w = pack_bf16x2(q.z - __bfloat162float(__float2bfloat16(q.z)),
                                   q.w - __bfloat162float(__float2bfloat16(q.w)));
                uint32_t off = row * 128 + ((u ^ (row & 7)) << 4);
                *reinterpret_cast<uint4*>(sAh + off) = hv;
                *reinterpret_cast<uint4*>(sAl + off) = lv;
            }
        }
        // ---- B tile load (hi & lo), swizzled ----
        constexpr int BU = NB * 8;
        for (int idx = tid; idx < 2 * BU; idx += 256) {
            int isLo = idx >= BU;
            int ii = isLo ? idx - BU : idx;
            int n = ii >> 3;
            int u = ii & 7;
            uint4 val = *reinterpret_cast<const uint4*>(
                (isLo ? Blv : Bhv) + (size_t)n * K_TOT + c * KC + u * 8);
            uint32_t off = n * 128 + ((u ^ (n & 7)) << 4);
            *reinterpret_cast<uint4*>((isLo ? sBl : sBh) + off) = val;
        }
        __syncthreads();

        // ---- compute: 3 passes (AhBh, AhBl, AlBh) x 4 k16 steps ----
#pragma unroll
        for (int p = 0; p < 3; p++) {
            uint32_t aBase = (p == 2) ? uAl : uAh;
            uint32_t bBase = (p == 1) ? uBl : uBh;
#pragma unroll
            for (int ks = 0; ks < 4; ks++) {
                uint32_t a[MF][4];
#pragma unroll
                for (int mf = 0; mf < MF; mf++) {
                    int row = warpM * WM + mf * 16 + (lane & 15);
                    int u = 2 * ks + (lane >> 4);
                    ldsm_x4(aBase + row * 128 + ((u ^ (row & 7)) << 4), a[mf]);
                }
#pragma unroll
                for (int nfp = 0; nfp < NF / 2; nfp++) {
                    int nrow = warpN * WN + nfp * 16 + ((lane >> 4) * 8) + (lane & 7);
                    int u = 2 * ks + ((lane >> 3) & 1);
                    uint32_t b[4];
                    ldsm_x4(bBase + nrow * 128 + ((u ^ (nrow & 7)) << 4), b);
#pragma unroll
                    for (int mf = 0; mf < MF; mf++) {
                        mma_bf16(acc[mf][2 * nfp + 0], a[mf], b[0], b[1]);
                        mma_bf16(acc[mf][2 * nfp + 1], a[mf], b[2], b[3]);
                    }
                }
                if (NF & 1) {
                    int l = lane & 15;
                    int nrow = warpN * WN + (NF - 1) * 8 + (l & 7);
                    int u = 2 * ks + (l >> 3);
                    uint32_t b[2];
                    ldsm_x2(bBase + nrow * 128 + ((u ^ (nrow & 7)) << 4), b);
#pragma unroll
                    for (int mf = 0; mf < MF; mf++)
                        mma_bf16(acc[mf][NF - 1], a[mf], b[0], b[1]);
                }
            }
        }
        __syncthreads();
    }

    // ---- epilogue ----
    if (EPI == 0) {
#pragma unroll
        for (int mf = 0; mf < MF; mf++) {
#pragma unroll
            for (int nf = 0; nf < NF; nf++) {
                int col = warpN * WN + nf * 8 + (lane & 3) * 2;
                float b0 = biasv[col], b1 = biasv[col + 1];
                int r0 = mrow0 + warpM * WM + mf * 16 + (lane >> 2);
                if (r0 < row_end) {
                    float2 v = make_float2(fmaxf(acc[mf][nf][0] + b0, 0.f),
                                           fmaxf(acc[mf][nf][1] + b1, 0.f));
                    *reinterpret_cast<float2*>(outp + (size_t)r0 * 128 + col) = v;
                }
                int r1 = r0 + 8;
                if (r1 < row_end) {
                    float2 v = make_float2(fmaxf(acc[mf][nf][2] + b0, 0.f),
                                           fmaxf(acc[mf][nf][3] + b1, 0.f));
                    *reinterpret_cast<float2*>(outp + (size_t)r1 * 128 + col) = v;
                }
            }
        }
    } else {
#pragma unroll
        for (int h = 0; h < 2; h++) {
            int row = mrow0 + wid * 16 + (lane >> 2) + h * 8;
            float v[2 * NF];
            float m = -INFINITY;
#pragma unroll
            for (int f = 0; f < NF; f++) {
                int col = f * 8 + (lane & 3) * 2;
                v[2 * f + 0] = acc[0][f][2 * h + 0] + biasv[col];
                v[2 * f + 1] = acc[0][f][2 * h + 1] + biasv[col + 1];
                m = fmaxf(m, fmaxf(v[2 * f], v[2 * f + 1]));
            }
            m = fmaxf(m, __shfl_xor_sync(0xFFFFFFFFu, m, 1));
            m = fmaxf(m, __shfl_xor_sync(0xFFFFFFFFu, m, 2));
            float s = 0.f;
#pragma unroll
            for (int j = 0; j < 2 * NF; j++) s += expf(v[j] - m);
            s += __shfl_xor_sync(0xFFFFFFFFu, s, 1);
            s += __shfl_xor_sync(0xFFFFFFFFu, s, 2);
            float l = m + logf(s);
            if (row < row_end) {
#pragma unroll
                for (int f = 0; f < NF; f++) {
                    int col = f * 8 + (lane & 3) * 2;
                    float2 o = make_float2(v[2 * f] - l, v[2 * f + 1] - l);
                    *reinterpret_cast<float2*>(outp + (size_t)row * NB + col) = o;
                }
            }
        }
    }
}

// ---------------- launch ----------------
extern "C" void kernel_launch(void* const* d_in, const int* in_sizes, int n_in,
                              void* d_out, int out_size)
{
    const float* x0      = (const float*)d_in[0];
    const float* emb1    = (const float*)d_in[1];
    const float* rel_w1  = (const float*)d_in[2];
    const float* root_w1 = (const float*)d_in[3];
    const float* root_b1 = (const float*)d_in[4];
    const float* rel_w2  = (const float*)d_in[5];
    const float* root_w2 = (const float*)d_in[6];
    const float* root_b2 = (const float*)d_in[7];
    const int*   eidx    = (const int*)d_in[8];
    const int*   etype   = (const int*)d_in[9];
    (void)in_sizes; (void)n_in; (void)out_size;

    const int* src = eidx;
    const int* dst = eidx + N_EDGES;
    float* out = (float*)d_out;

    void *p_cnt, *p_h1r, *p_B1h, *p_B1l, *p_B2h, *p_B2l;
    cudaGetSymbolAddress(&p_cnt, g_cnt);
    cudaGetSymbolAddress(&p_h1r, g_h1r);
    cudaGetSymbolAddress(&p_B1h, g_B1h);
    cudaGetSymbolAddress(&p_B1l, g_B1l);
    cudaGetSymbolAddress(&p_B2h, g_B2h);
    cudaGetSymbolAddress(&p_B2l, g_B2l);

    constexpr int SMEM1 = 2 * (128 * KC * 2) + 2 * (128 * KC * 2);  // 65536
    constexpr int SMEM2 = 2 * (128 * KC * 2) + 2 * (40 * KC * 2);   // 43008
    cudaFuncSetAttribute(gemm_kernel<128, 0, 0>, cudaFuncAttributeMaxDynamicSharedMemorySize, SMEM1);
    cudaFuncSetAttribute(gemm_kernel<40, 1, 1>,  cudaFuncAttributeMaxDynamicSharedMemorySize, SMEM2);

    // B weight split (tiny)
    prepB_kernel<128><<<(2 * 128 * K_TOT + 255) / 256, 256>>>(
        rel_w1, root_w1, (__nv_bfloat16*)p_B1h, (__nv_bfloat16*)p_B1l);
    prepB_kernel<40><<<(2 * 40 * K_TOT + 255) / 256, 256>>>(
        rel_w2, root_w2, (__nv_bfloat16*)p_B2h, (__nv_bfloat16*)p_B2l);

    // CSR build: count -> scan -> scatter
    cudaMemsetAsync(p_cnt, 0, sizeof(int) * SEG);
    count_kernel<<<(N_EDGES + 255) / 256, 256>>>(dst, etype);
    scanA_kernel<<<NBLK, 256>>>();
    scanB_kernel<<<1, 512>>>();
    scanC_kernel<<<NBLK, 256>>>();
    scatter_kernel<<<(N_EDGES + 255) / 256, 256>>>(src, dst, etype);

    // layer 1: atomic-free aggregation (bf16 hi/lo) + GEMM (rel+root+bias+relu) -> g_h1r
    agg_kernel<0><<<(SEG * 32 + 255) / 256, 256>>>(x0, emb1);
    gemm_kernel<128, 0, 0><<<TILES0 + TILES1, 256, SMEM1>>>(
        x0, emb1, (const __nv_bfloat16*)p_B1h, (const __nv_bfloat16*)p_B1l,
        root_b1, (float*)p_h1r);

    // layer 2: aggregation + GEMM (rel+root+bias+log_softmax) -> d_out
    agg_kernel<1><<<(SEG * 32 + 255) / 256, 256>>>((const float*)p_h1r, nullptr);
    gemm_kernel<40, 1, 1><<<TILES0 + TILES1, 256, SMEM2>>>(
        (const float*)p_h1r, nullptr, (const __nv_bfloat16*)p_B2h, (const __nv_bfloat16*)p_B2l,
        root_b2, out);
}

// round 7
// speedup vs baseline: 2.4624x; 1.5205x over previous
#include <cuda_runtime.h>
#include <cuda_bf16.h>
#include <cstdint>
#include <math.h>

// ---------------- problem constants ----------------
constexpr int N_NODES = 50000;
constexpr int N0      = 30000;
constexpr int N_EDGES = 600000;
constexpr int NT      = 8;
constexpr int K_TOT   = 1152;          // 8*128 rel + 128 root
constexpr int KC      = 64;
constexpr int NCHUNK  = K_TOT / KC;    // 18
constexpr int TILES0  = 235;           // ceil(30000/128)
constexpr int TILES1  = 157;           // ceil(20000/128)
constexpr int N_PAD   = (TILES0 + TILES1) * 128;   // 50176 padded rows
constexpr int SEG     = NT * N_NODES;  // 400000 CSR segments, key = t*N + d
constexpr int NBLK    = (SEG + 1023) / 1024;  // 391

// ---------------- device scratch ----------------
__device__ float g_h1r[(size_t)N_NODES * 128];     // relu(h1), 25.6 MB
__device__ int   g_cnt[SEG];
__device__ int   g_off[SEG + 1];
__device__ int   g_cur[SEG];
__device__ int   g_esrc[N_EDGES];
__device__ int   g_bsum[NBLK];
__device__ int   g_bpre[NBLK];
// A buffers: [N_PAD][1152] bf16 hi/lo; padded rows never written -> stay zero.
__device__ __align__(16) __nv_bfloat16 g_aggh[(size_t)N_PAD * K_TOT];  // 115.6 MB
__device__ __align__(16) __nv_bfloat16 g_aggl[(size_t)N_PAD * K_TOT];  // 115.6 MB
__device__ __align__(16) __nv_bfloat16 g_B1h[2 * 128 * K_TOT];
__device__ __align__(16) __nv_bfloat16 g_B1l[2 * 128 * K_TOT];
__device__ __align__(16) __nv_bfloat16 g_B2h[2 * 40 * K_TOT];
__device__ __align__(16) __nv_bfloat16 g_B2l[2 * 40 * K_TOT];

// ---------------- helpers ----------------
__device__ __forceinline__ uint32_t smem_u32(const void* p) {
    uint32_t a;
    asm("{ .reg .u64 t; cvta.to.shared.u64 t, %1; cvt.u32.u64 %0, t; }" : "=r"(a) : "l"(p));
    return a;
}
__device__ __forceinline__ uint32_t pack_bf16x2(float a, float b) {
    __nv_bfloat162 t = __floats2bfloat162_rn(a, b);
    return *reinterpret_cast<uint32_t*>(&t);
}
__device__ __forceinline__ void cp16(uint32_t s, const void* g) {
    asm volatile("cp.async.cg.shared.global [%0], [%1], 16;" :: "r"(s), "l"(g));
}
__device__ __forceinline__ void cp_commit() {
    asm volatile("cp.async.commit_group;" ::: "memory");
}
template<int N>
__device__ __forceinline__ void cp_wait() {
    asm volatile("cp.async.wait_group %0;" :: "n"(N) : "memory");
}
__device__ __forceinline__ void ldsm_x4(uint32_t addr, uint32_t* r) {
    asm volatile("ldmatrix.sync.aligned.m8n8.x4.shared.b16 {%0,%1,%2,%3}, [%4];"
                 : "=r"(r[0]), "=r"(r[1]), "=r"(r[2]), "=r"(r[3]) : "r"(addr));
}
__device__ __forceinline__ void ldsm_x2(uint32_t addr, uint32_t* r) {
    asm volatile("ldmatrix.sync.aligned.m8n8.x2.shared.b16 {%0,%1}, [%2];"
                 : "=r"(r[0]), "=r"(r[1]) : "r"(addr));
}
__device__ __forceinline__ void mma_bf16(float* c, const uint32_t* a, uint32_t b0, uint32_t b1) {
    asm volatile(
        "mma.sync.aligned.m16n8k16.row.col.f32.bf16.bf16.f32 "
        "{%0,%1,%2,%3}, {%4,%5,%6,%7}, {%8,%9}, {%0,%1,%2,%3};"
        : "+f"(c[0]), "+f"(c[1]), "+f"(c[2]), "+f"(c[3])
        : "r"(a[0]), "r"(a[1]), "r"(a[2]), "r"(a[3]), "r"(b0), "r"(b1));
}

// ---------------- CSR build ----------------
__global__ void count_kernel(const int* __restrict__ dst, const int* __restrict__ et) {
    int e = blockIdx.x * blockDim.x + threadIdx.x;
    if (e < N_EDGES) atomicAdd(&g_cnt[et[e] * N_NODES + dst[e]], 1);
}

__global__ void scanA_kernel() {
    __shared__ int sm[256];
    int base = blockIdx.x * 1024 + threadIdx.x * 4;
    int s = 0;
#pragma unroll
    for (int j = 0; j < 4; j++) { int i = base + j; if (i < SEG) s += g_cnt[i]; }
    sm[threadIdx.x] = s; __syncthreads();
    for (int off = 128; off > 0; off >>= 1) {
        if (threadIdx.x < off) sm[threadIdx.x] += sm[threadIdx.x + off];
        __syncthreads();
    }
    if (threadIdx.x == 0) g_bsum[blockIdx.x] = sm[0];
}

__global__ void scanB_kernel() {
    __shared__ int sm[512];
    int tid = threadIdx.x;
    int v = (tid < NBLK) ? g_bsum[tid] : 0;
    sm[tid] = v; __syncthreads();
    for (int off = 1; off < 512; off <<= 1) {
        int t = (tid >= off) ? sm[tid - off] : 0;
        __syncthreads();
        sm[tid] += t;
        __syncthreads();
    }
    if (tid < NBLK) g_bpre[tid] = sm[tid] - v;
    if (tid == 0) g_off[SEG] = N_EDGES;
}

__global__ void scanC_kernel() {
    __shared__ int sm[256];
    int tid = threadIdx.x;
    int base = blockIdx.x * 1024 + tid * 4;
    int c[4]; int ls = 0;
#pragma unroll
    for (int j = 0; j < 4; j++) { int i = base + j; c[j] = (i < SEG) ? g_cnt[i] : 0; ls += c[j]; }
    sm[tid] = ls; __syncthreads();
    for (int off = 1; off < 256; off <<= 1) {
        int t = (tid >= off) ? sm[tid - off] : 0;
        __syncthreads();
        sm[tid] += t;
        __syncthreads();
    }
    int run = g_bpre[blockIdx.x] + sm[tid] - ls;
#pragma unroll
    for (int j = 0; j < 4; j++) {
        int i = base + j;
        if (i < SEG) {
            g_off[i] = run; g_cur[i] = run;
            run += c[j];
        }
    }
}

__global__ void scatter_kernel(const int* __restrict__ src, const int* __restrict__ dst,
                               const int* __restrict__ et) {
    int e = blockIdx.x * blockDim.x + threadIdx.x;
    if (e >= N_EDGES) return;
    int key = et[e] * N_NODES + dst[e];
    int pos = atomicAdd(&g_cur[key], 1);
    g_esrc[pos] = src[e];
}

// ---------------- aggregation + root fill (atomic-free, warp per unit) ----------------
// units [0,SEG): agg[d][t*128+c] = mean of source rows (zeros if empty)
// units [SEG,SEG+N): agg[n][1024+c] = own features (root block)
template<int SRC>
__global__ void agg_kernel(const float* __restrict__ R0, const float* __restrict__ R1)
{
    int w = (blockIdx.x * blockDim.x + threadIdx.x) >> 5;
    int lane = threadIdx.x & 31;
    if (w < SEG) {
        int t = w / N_NODES;
        int d = w - t * N_NODES;
        int o0 = g_off[w], o1 = g_off[w + 1];
        float4 acc = make_float4(0.f, 0.f, 0.f, 0.f);
        for (int e = o0; e < o1; e++) {
            int s = g_esrc[e];
            const float* xs = (SRC == 0)
                ? ((s < N0) ? R0 + (size_t)s * 128 : R1 + (size_t)(s - N0) * 128)
                : R0 + (size_t)s * 128;
            float4 v = reinterpret_cast<const float4*>(xs)[lane];
            acc.x += v.x; acc.y += v.y; acc.z += v.z; acc.w += v.w;
        }
        int len = o1 - o0;
        float inv = 1.0f / (float)(len < 1 ? 1 : len);
        acc.x *= inv; acc.y *= inv; acc.z *= inv; acc.w *= inv;
        uint2 hv, lv;
        hv.x = pack_bf16x2(acc.x, acc.y);
        hv.y = pack_bf16x2(acc.z, acc.w);
        lv.x = pack_bf16x2(acc.x - __bfloat162float(__float2bfloat16(acc.x)),
                           acc.y - __bfloat162float(__float2bfloat16(acc.y)));
        lv.y = pack_bf16x2(acc.z - __bfloat162float(__float2bfloat16(acc.z)),
                           acc.w - __bfloat162float(__float2bfloat16(acc.w)));
        size_t o = (size_t)d * K_TOT + t * 128 + lane * 4;
        *reinterpret_cast<uint2*>(g_aggh + o) = hv;
        *reinterpret_cast<uint2*>(g_aggl + o) = lv;
    } else if (w < SEG + N_NODES) {
        int d = w - SEG;
        const float* xs = (SRC == 0)
            ? ((d < N0) ? R0 + (size_t)d * 128 : R1 + (size_t)(d - N0) * 128)
            : R0 + (size_t)d * 128;
        float4 v = reinterpret_cast<const float4*>(xs)[lane];
        uint2 hv, lv;
        hv.x = pack_bf16x2(v.x, v.y);
        hv.y = pack_bf16x2(v.z, v.w);
        lv.x = pack_bf16x2(v.x - __bfloat162float(__float2bfloat16(v.x)),
                           v.y - __bfloat162float(__float2bfloat16(v.y)));
        lv.y = pack_bf16x2(v.z - __bfloat162float(__float2bfloat16(v.z)),
                           v.w - __bfloat162float(__float2bfloat16(v.w)));
        size_t o = (size_t)d * K_TOT + 1024 + lane * 4;
        *reinterpret_cast<uint2*>(g_aggh + o) = hv;
        *reinterpret_cast<uint2*>(g_aggl + o) = lv;
    }
}

// ---------------- B prep ----------------
template<int NB>
__global__ void prepB_kernel(const float* __restrict__ rel_w, const float* __restrict__ root_w,
                             __nv_bfloat16* __restrict__ Bh, __nv_bfloat16* __restrict__ Bl)
{
    int i = blockIdx.x * blockDim.x + threadIdx.x;
    if (i >= 2 * NB * K_TOT) return;
    int k = i % K_TOT;
    int n = (i / K_TOT) % NB;
    int v = i / (K_TOT * NB);
    float w = (k < NT * 128) ? rel_w[(k >> 7) * NB * 128 + n * 128 + (k & 127)]
                             : root_w[v * NB * 128 + n * 128 + (k - NT * 128)];
    __nv_bfloat16 h = __float2bfloat16(w);
    Bh[i] = h;
    Bl[i] = __float2bfloat16(w - __bfloat162float(h));
}

// ---------------- bf16x3 mma.sync GEMM with cp.async double buffering ----------------
// D[128 x BN] per CTA.  A from g_aggh/g_aggl ([N_PAD][1152], uniform chunks).
// EPI 0: relu(D+bias) -> outp[row*128 + col], NBtot=128, grid.y=2 (BN=64)
// EPI 1: log_softmax(D+bias) -> outp[row*40 + col], NBtot=40, grid.y=1 (BN=40)
template<int BN, int EPI>
__global__ void __launch_bounds__(256, 2) gemm_kernel(
    const __nv_bfloat16* __restrict__ Bh, const __nv_bfloat16* __restrict__ Bl,
    const float* __restrict__ bias, float* __restrict__ outp)
{
    constexpr int NBT = (EPI == 0) ? 128 : 40;
    constexpr int WARPS_M = (BN == 64) ? 4 : 8;
    constexpr int WARPS_N = (BN == 64) ? 2 : 1;
    constexpr int WM = 128 / WARPS_M;          // 32 or 16
    constexpr int WN = BN / WARPS_N;           // 32 or 40
    constexpr int MF = WM / 16;                // 2 or 1
    constexpr int NF = WN / 8;                 // 4 or 5
    constexpr int A_BYTES = 128 * KC * 2;      // 16384
    constexpr int B_BYTES = BN * KC * 2;
    constexpr int STAGE = 2 * A_BYTES + 2 * B_BYTES;

    extern __shared__ char smem[];
    const uint32_t sbase = smem_u32(smem);

    const int tid  = threadIdx.x;
    const int wid  = tid >> 5;
    const int lane = tid & 31;
    const int warpM = wid % WARPS_M;
    const int warpN = wid / WARPS_M;

    const int bx = blockIdx.x;
    const int nbase = blockIdx.y * BN;
    const int var = (bx < TILES0) ? 0 : 1;
    const int mrow0 = var ? (N0 + (bx - TILES0) * 128) : (bx * 128);
    const int row_end = var ? N_NODES : N0;
    const __nv_bfloat16* Bhv = Bh + (size_t)var * NBT * K_TOT;
    const __nv_bfloat16* Blv = Bl + (size_t)var * NBT * K_TOT;
    const float* biasv = bias + var * NBT;
    const size_t aggRow0 = (size_t)mrow0 * K_TOT;

    float acc[MF][NF][4];
#pragma unroll
    for (int i = 0; i < MF; i++)
#pragma unroll
        for (int j = 0; j < NF; j++)
#pragma unroll
            for (int q = 0; q < 4; q++) acc[i][j][q] = 0.f;

    // ---- cp.async issue for chunk c into stage c&1 ----
    auto issue = [&](int c) {
        uint32_t ust = sbase + (c & 1) * STAGE;
        // A: 2048 x 16B (hi then lo)
#pragma unroll
        for (int i = 0; i < 8; i++) {
            int idx = tid + i * 256;
            int isLo = idx >= 1024;
            int ii = idx & 1023;
            int row = ii >> 3, u = ii & 7;
            const __nv_bfloat16* gp = (isLo ? g_aggl : g_aggh)
                + aggRow0 + (size_t)row * K_TOT + c * KC + u * 8;
            cp16(ust + (isLo ? A_BYTES : 0) + row * 128 + ((u ^ (row & 7)) << 4), gp);
        }
        // B: 2*BN*8 x 16B
        constexpr int BITEMS = 2 * BN * 8;
#pragma unroll
        for (int j = 0; j < (BITEMS + 255) / 256; j++) {
            int idx = tid + j * 256;
            if ((BITEMS % 256 == 0) || idx < BITEMS) {
                int isLo = idx >= BN * 8;
                int ii = isLo ? idx - BN * 8 : idx;
                int n = ii >> 3, u = ii & 7;
                const __nv_bfloat16* gp = (isLo ? Blv : Bhv)
                    + (size_t)(nbase + n) * K_TOT + c * KC + u * 8;
                cp16(ust + 2 * A_BYTES + (isLo ? B_BYTES : 0) + n * 128 + ((u ^ (n & 7)) << 4), gp);
            }
        }
        cp_commit();
    };

    issue(0);
    for (int c = 0; c < NCHUNK; c++) {
        if (c + 1 < NCHUNK) { issue(c + 1); cp_wait<1>(); }
        else                { cp_wait<0>(); }
        __syncthreads();

        const uint32_t ust = sbase + (c & 1) * STAGE;
        const uint32_t uAh = ust, uAl = ust + A_BYTES;
        const uint32_t uBh = ust + 2 * A_BYTES, uBl = uBh + B_BYTES;

#pragma unroll
        for (int p = 0; p < 3; p++) {
            uint32_t aBase = (p == 2) ? uAl : uAh;
            uint32_t bBase = (p == 1) ? uBl : uBh;
#pragma unroll
            for (int ks = 0; ks < 4; ks++) {
                uint32_t a[MF][4];
#pragma unroll
                for (int mf = 0; mf < MF; mf++) {
                    int row = warpM * WM + mf * 16 + (lane & 15);
                    int u = 2 * ks + (lane >> 4);
                    ldsm_x4(aBase + row * 128 + ((u ^ (row & 7)) << 4), a[mf]);
                }
#pragma unroll
                for (int nfp = 0; nfp < NF / 2; nfp++) {
                    int nrow = warpN * WN + nfp * 16 + ((lane >> 4) * 8) + (lane & 7);
                    int u = 2 * ks + ((lane >> 3) & 1);
                    uint32_t b[4];
                    ldsm_x4(bBase + nrow * 128 + ((u ^ (nrow & 7)) << 4), b);
#pragma unroll
                    for (int mf = 0; mf < MF; mf++) {
                        mma_bf16(acc[mf][2 * nfp + 0], a[mf], b[0], b[1]);
                        mma_bf16(acc[mf][2 * nfp + 1], a[mf], b[2], b[3]);
                    }
                }
                if (NF & 1) {
                    int l = lane & 15;
                    int nrow = warpN * WN + (NF - 1) * 8 + (l & 7);
                    int u = 2 * ks + (l >> 3);
                    uint32_t b[2];
                    ldsm_x2(bBase + nrow * 128 + ((u ^ (nrow & 7)) << 4), b);
#pragma unroll
                    for (int mf = 0; mf < MF; mf++)
                        mma_bf16(acc[mf][NF - 1], a[mf], b[0], b[1]);
                }
            }
        }
        __syncthreads();
    }

    // ---- epilogue ----
    if (EPI == 0) {
#pragma unroll
        for (int mf = 0; mf < MF; mf++) {
#pragma unroll
            for (int nf = 0; nf < NF; nf++) {
                int col = nbase + warpN * WN + nf * 8 + (lane & 3) * 2;
                float b0 = biasv[col], b1 = biasv[col + 1];
                int r0 = mrow0 + warpM * WM + mf * 16 + (lane >> 2);
                if (r0 < row_end) {
                    float2 v = make_float2(fmaxf(acc[mf][nf][0] + b0, 0.f),
                                           fmaxf(acc[mf][nf][1] + b1, 0.f));
                    *reinterpret_cast<float2*>(outp + (size_t)r0 * 128 + col) = v;
                }
                int r1 = r0 + 8;
                if (r1 < row_end) {
                    float2 v = make_float2(fmaxf(acc[mf][nf][2] + b0, 0.f),
                                           fmaxf(acc[mf][nf][3] + b1, 0.f));
                    *reinterpret_cast<float2*>(outp + (size_t)r1 * 128 + col) = v;
                }
            }
        }
    } else {
#pragma unroll
        for (int h = 0; h < 2; h++) {
            int row = mrow0 + wid * 16 + (lane >> 2) + h * 8;
            float v[2 * NF];
            float m = -INFINITY;
#pragma unroll
            for (int f = 0; f < NF; f++) {
                int col = f * 8 + (lane & 3) * 2;
                v[2 * f + 0] = acc[0][f][2 * h + 0] + biasv[col];
                v[2 * f + 1] = acc[0][f][2 * h + 1] + biasv[col + 1];
                m = fmaxf(m, fmaxf(v[2 * f], v[2 * f + 1]));
            }
            m = fmaxf(m, __shfl_xor_sync(0xFFFFFFFFu, m, 1));
            m = fmaxf(m, __shfl_xor_sync(0xFFFFFFFFu, m, 2));
            float s = 0.f;
#pragma unroll
            for (int j = 0; j < 2 * NF; j++) s += expf(v[j] - m);
            s += __shfl_xor_sync(0xFFFFFFFFu, s, 1);
            s += __shfl_xor_sync(0xFFFFFFFFu, s, 2);
            float l = m + logf(s);
            if (row < row_end) {
#pragma unroll
                for (int f = 0; f < NF; f++) {
                    int col = f * 8 + (lane & 3) * 2;
                    float2 o = make_float2(v[2 * f] - l, v[2 * f + 1] - l);
                    *reinterpret_cast<float2*>(outp + (size_t)row * 40 + col) = o;
                }
            }
        }
    }
}

// ---------------- launch ----------------
extern "C" void kernel_launch(void* const* d_in, const int* in_sizes, int n_in,
                              void* d_out, int out_size)
{
    const float* x0      = (const float*)d_in[0];
    const float* emb1    = (const float*)d_in[1];
    const float* rel_w1  = (const float*)d_in[2];
    const float* root_w1 = (const float*)d_in[3];
    const float* root_b1 = (const float*)d_in[4];
    const float* rel_w2  = (const float*)d_in[5];
    const float* root_w2 = (const float*)d_in[6];
    const float* root_b2 = (const float*)d_in[7];
    const int*   eidx    = (const int*)d_in[8];
    const int*   etype   = (const int*)d_in[9];
    (void)in_sizes; (void)n_in; (void)out_size;

    const int* src = eidx;
    const int* dst = eidx + N_EDGES;
    float* out = (float*)d_out;

    void *p_cnt, *p_h1r, *p_B1h, *p_B1l, *p_B2h, *p_B2l;
    cudaGetSymbolAddress(&p_cnt, g_cnt);
    cudaGetSymbolAddress(&p_h1r, g_h1r);
    cudaGetSymbolAddress(&p_B1h, g_B1h);
    cudaGetSymbolAddress(&p_B1l, g_B1l);
    cudaGetSymbolAddress(&p_B2h, g_B2h);
    cudaGetSymbolAddress(&p_B2l, g_B2l);

    constexpr int SMEM1 = 2 * (2 * 128 * KC * 2 + 2 * 64 * KC * 2);  // 98304
    constexpr int SMEM2 = 2 * (2 * 128 * KC * 2 + 2 * 40 * KC * 2);  // 86016
    cudaFuncSetAttribute(gemm_kernel<64, 0>, cudaFuncAttributeMaxDynamicSharedMemorySize, SMEM1);
    cudaFuncSetAttribute(gemm_kernel<40, 1>, cudaFuncAttributeMaxDynamicSharedMemorySize, SMEM2);

    // B weight split (tiny)
    prepB_kernel<128><<<(2 * 128 * K_TOT + 255) / 256, 256>>>(
        rel_w1, root_w1, (__nv_bfloat16*)p_B1h, (__nv_bfloat16*)p_B1l);
    prepB_kernel<40><<<(2 * 40 * K_TOT + 255) / 256, 256>>>(
        rel_w2, root_w2, (__nv_bfloat16*)p_B2h, (__nv_bfloat16*)p_B2l);

    // CSR build: count -> scan -> scatter
    cudaMemsetAsync(p_cnt, 0, sizeof(int) * SEG);
    count_kernel<<<(N_EDGES + 255) / 256, 256>>>(dst, etype);
    scanA_kernel<<<NBLK, 256>>>();
    scanB_kernel<<<1, 512>>>();
    scanC_kernel<<<NBLK, 256>>>();
    scatter_kernel<<<(N_EDGES + 255) / 256, 256>>>(src, dst, etype);

    const int AGG_BLOCKS = ((SEG + N_NODES) * 32 + 255) / 256;

    // layer 1: aggregation (+root fill) + pipelined GEMM -> g_h1r
    agg_kernel<0><<<AGG_BLOCKS, 256>>>(x0, emb1);
    gemm_kernel<64, 0><<<dim3(TILES0 + TILES1, 2), 256, SMEM1>>>(
        (const __nv_bfloat16*)p_B1h, (const __nv_bfloat16*)p_B1l, root_b1, (float*)p_h1r);

    // layer 2: aggregation (+root fill) + pipelined GEMM -> d_out
    agg_kernel<1><<<AGG_BLOCKS, 256>>>((const float*)p_h1r, nullptr);
    gemm_kernel<40, 1><<<dim3(TILES0 + TILES1, 1), 256, SMEM2>>>(
        (const __nv_bfloat16*)p_B2h, (const __nv_bfloat16*)p_B2l, root_b2, out);
}